// round 17
// baseline (speedup 1.0000x reference)
#include <cuda_runtime.h>
#include <cuda_pipeline.h>
#include <cstdint>

// PSRoIPool, cp.async double-buffered multi-plane kernel.
// x (4, 1029, 96, 96) fp32, rois (512,5) fp32, out (512, 21, 7, 7) fp32.
// Grid (49, 3, 4): block = (ij, c_group, b). Decode roi bounds once
// (ballot-compacted), then pipeline over 7 planes: cp.async-stage plane c+1
// into the other buffer while scanning+gathering plane c.
//
// NUMERIC CONTRACT (verified R5): bin sizes are reciprocal-multiplies
// __fmul_rn(extent, fl(1/7)) — NOT divisions. Do not change.

#define C_TOT   1029
#define C_OUT   21
#define PH      7
#define PW      7
#define HH      96
#define WW      96
#define W4      24            // float4s per row
#define WP4     25            // padded float4 row stride (100 floats)
#define WPF     (WP4*4)
#define PLANE   (HH*WW)
#define BUF4    (HH*WP4)      // float4s per buffer (2400)
#define KROIS   512
#define NBATCH  4
#define SCALE   0.0625f
#define RCP7    0.1428571492433547973632812500f   // fl(1/7) = 0x3E124925
#define THREADS 256
#define CGRP    7             // planes per block
#define DSMEM   (2 * BUF4 * 16)   // 76800 B dynamic smem

__global__ __launch_bounds__(THREADS) void psroi_pipe(
    const float* __restrict__ x,
    const float* __restrict__ rois,
    float* __restrict__ out)
{
    extern __shared__ float4 buf[];        // 2 plane buffers
    __shared__ int      s_kk [KROIS];
    __shared__ uint32_t s_bnd[KROIS];
    __shared__ int      s_cnt;

    const int ijx  = blockIdx.x;           // 0..48
    const int cg   = blockIdx.y;           // 0..2
    const int b    = blockIdx.z;           // 0..3
    const int i    = ijx / PW;
    const int j    = ijx - i * PW;
    const int tid  = threadIdx.x;
    const int lane = tid & 31;

    if (tid == 0) s_cnt = 0;
    __syncthreads();

    // ---- Decode + ballot-compact rois of batch b (once per block).
    #pragma unroll
    for (int t = 0; t < 2; ++t) {
        const int k = tid + t * THREADS;
        const float* roi = rois + k * 5;
        const bool match = ((int)__ldg(roi) == b);
        const unsigned m = __ballot_sync(0xffffffffu, match);
        int base;
        if (lane == 0) base = atomicAdd(&s_cnt, __popc(m));
        base = __shfl_sync(0xffffffffu, base, 0);
        if (match) {
            const int sw = (int)floorf(__fmaf_rn(__ldg(roi + 1), SCALE, 0.5f));
            const int sh = (int)floorf(__fmaf_rn(__ldg(roi + 2), SCALE, 0.5f));
            const int ew = (int)floorf(__fmaf_rn(__ldg(roi + 3), SCALE, 0.5f));
            const int eh = (int)floorf(__fmaf_rn(__ldg(roi + 4), SCALE, 0.5f));
            const float bin_h = __fmul_rn((float)max(eh - sh, 1), RCP7);
            const float bin_w = __fmul_rn((float)max(ew - sw, 1), RCP7);
            const int hs = min(max((int)floorf(__fmul_rn((float)i,       bin_h)) + sh, 0), HH);
            const int he = min(max((int)ceilf (__fmul_rn((float)(i + 1), bin_h)) + sh, 0), HH);
            const int ws = min(max((int)floorf(__fmul_rn((float)j,       bin_w)) + sw, 0), WW);
            const int we = min(max((int)ceilf (__fmul_rn((float)(j + 1), bin_w)) + sw, 0), WW);
            const int pos = base + __popc(m & ((1u << lane) - 1u));
            s_kk [pos] = k;
            s_bnd[pos] = (uint32_t)hs | ((uint32_t)he << 8)
                       | ((uint32_t)ws << 16) | ((uint32_t)we << 24);
        }
    }
    __syncthreads();
    const int cnt = s_cnt;
    const int c0  = cg * CGRP;

    // Async stage of plane (b, c*49+ijx) into buffer pb.
    auto stage = [&](int c, int pb) {
        const float4* __restrict__ src4 =
            (const float4*)(x + ((size_t)b * C_TOT + (c * (PH * PW) + ijx)) * PLANE);
        float4* __restrict__ d = buf + pb * BUF4;
        #pragma unroll
        for (int q = 0; q < PLANE / 4 / THREADS; ++q) {  // 9
            const int e   = tid + q * THREADS;
            const int row = e / W4;
            const int c4  = e - row * W4;
            __pipeline_memcpy_async(&d[row * WP4 + c4], &src4[e], 16);
        }
        __pipeline_commit();
    };

    stage(c0, 0);                          // prologue

    for (int cc = 0; cc < CGRP; ++cc) {
        const int pb = cc & 1;
        if (cc + 1 < CGRP) {
            stage(c0 + cc + 1, pb ^ 1);    // prefetch next plane
            __pipeline_wait_prior(1);      // current plane's group done
        } else {
            __pipeline_wait_prior(0);
        }
        __syncthreads();

        float4* const sp4 = buf + pb * BUF4;
        float*  const sp  = (float*)sp4;

        // Row prefix (float4 pipeline, short carry chain).
        if (tid < HH) {
            float4* __restrict__ rr = sp4 + tid * WP4;
            float run = 0.0f;
            #pragma unroll
            for (int q = 0; q < W4; ++q) {
                float4 v = rr[q];
                const float s01 = v.x + v.y;
                const float s4  = s01 + (v.z + v.w);
                float4 o;
                o.x = run + v.x;
                o.y = run + s01;
                o.z = o.y + v.z;
                o.w = run + s4;
                rr[q] = o;
                run   = o.w;
            }
        }
        __syncthreads();

        // Gather: prefix-difference row sums.
        const int p = (c0 + cc) * (PH * PW) + ijx;
        for (int n = tid; n < cnt; n += THREADS) {
            const uint32_t bnd = s_bnd[n];
            const int hs = bnd & 0xff;
            const int he = (bnd >> 8) & 0xff;
            const int ws = (bnd >> 16) & 0xff;
            const int we = bnd >> 24;

            const int area = (he - hs) * (we - ws);
            float val = 0.0f;
            if (area > 0) {
                float acc = 0.0f;
                const float* __restrict__ right = sp + (we - 1);
                if (ws > 0) {
                    const float* __restrict__ left = sp + (ws - 1);
                    for (int hy = hs; hy < he; ++hy)
                        acc += right[hy * WPF] - left[hy * WPF];
                } else {
                    for (int hy = hs; hy < he; ++hy)
                        acc += right[hy * WPF];
                }
                val = __fdiv_rn(acc, (float)area);
            }
            out[s_kk[n] * C_TOT + p] = val;
        }
        __syncthreads();   // buffer pb free before cc+2 prefetches into it
    }
}

extern "C" void kernel_launch(void* const* d_in, const int* in_sizes, int n_in,
                              void* d_out, int out_size)
{
    const float* x;
    const float* rois;
    if (n_in >= 2 && in_sizes[0] == KROIS * 5) {
        rois = (const float*)d_in[0];
        x    = (const float*)d_in[1];
    } else {
        x    = (const float*)d_in[0];
        rois = (const float*)d_in[1];
    }
    float* out = (float*)d_out;

    cudaFuncSetAttribute(psroi_pipe,
                         cudaFuncAttributeMaxDynamicSharedMemorySize, DSMEM);
    dim3 grid(PH * PW, C_OUT / CGRP, NBATCH);   // (49, 3, 4)
    psroi_pipe<<<grid, THREADS, DSMEM>>>(x, rois, out);
}